// round 12
// baseline (speedup 1.0000x reference)
#include <cuda_runtime.h>
#include <cuda_bf16.h>
#include <cuda_fp16.h>
#include <math.h>

#define NN 100000
#define NE 600000
#define DD 128
#define TD 384
#define NG 64
#define ROUNDS 8

// ---------------- scratch ----------------
__device__ float    g_x[NN * DD];            // fp32 node state (GRU h path, pooling)
__device__ unsigned g_xh[NN * 64];           // half2-packed shadow of x (message path)
__device__ unsigned g_S[NN * 192];           // aggregated sums, packed half2
__device__ unsigned g_WcatP[12 * 2048];      // fp16 pair-packed agg weights
__device__ unsigned g_WcombP[3 * 8 * 2048];  // fp16 pair-packed gate weights
__device__ int   g_deg[NN];
__device__ int   g_rowoff[NN + 1];
__device__ int   g_cursor[NN];
__device__ int   g_packed[NE];
__device__ int   g_cnt[NN * 3];
__device__ int   g_bsums[128];
__device__ int   g_scan_ctr;
__device__ float g_pooled[NG * DD];
__device__ int   g_gcount[NG];
__device__ int   g_gstart[NG + 1];

__device__ __forceinline__ unsigned pack2(float a, float b) {
    __half2 h = __floats2half2_rn(a, b);
    return *(unsigned*)&h;
}

// ---------------- cp.async helpers ----------------
__device__ __forceinline__ void cp16(unsigned dst, const void* src, int bytes) {
    asm volatile("cp.async.ca.shared.global [%0], [%1], 16, %2;"
                 :: "r"(dst), "l"(src), "r"(bytes) : "memory");
}
#define CP_COMMIT() asm volatile("cp.async.commit_group;" ::: "memory")
#define CP_WAIT1() asm volatile("cp.async.wait_group 1;" ::: "memory")
#define CP_WAIT0() asm volatile("cp.async.wait_group 0;" ::: "memory")

// ---------------- setup ----------------
__global__ void mega_setup(const int* __restrict__ x_type, const int* __restrict__ x_tok,
                           const float* __restrict__ x_small,
                           const float* __restrict__ type_emb, const float* __restrict__ tok_emb,
                           const float* __restrict__ msg_W,
                           const float* __restrict__ W_ih, const float* __restrict__ W_hh) {
    long long idx = (long long)blockIdx.x * blockDim.x + threadIdx.x;
    const long long R0 = (long long)NN * 128;
    if (idx < R0) {
        int n = (int)(idx >> 7);
        int j = (int)(idx & 127);
        float v;
        if (j < 32)       v = type_emb[x_type[n] * 32 + j];
        else if (j < 64)  v = tok_emb[x_tok[n] * 32 + (j - 32)];
        else              v = x_small[n * 64 + (j - 64)];
        g_x[idx] = v;
        ((__half*)g_xh)[idx] = __float2half(v);
        return;
    }
    long long i1 = idx - R0;
    if (i1 < 12 * 2048) {
        int c = (int)(i1 >> 11);
        int r = (int)(i1 & 2047);
        int h = r & 1;
        int tg = (r >> 1) & 3;
        int col = (r >> 3) & 127;
        int ks = r >> 10;
        int k0 = c * 32 + ks * 16 + h * 8 + tg * 2;
        int t0 = k0 >> 7, i0 = k0 & 127;
        int k1 = k0 + 1;
        int t1 = k1 >> 7, i1b = k1 & 127;
        g_WcatP[i1] = pack2(msg_W[t0 * 16384 + col * 128 + i0],
                            msg_W[t1 * 16384 + col * 128 + i1b]);
        return;
    }
    long long i2 = i1 - 12 * 2048;
    if (i2 < 3LL * 8 * 2048) {
        int gate = (int)(i2 >> 14);
        int r2 = (int)(i2 & 16383);
        int c = r2 >> 11;
        int r = r2 & 2047;
        int h = r & 1;
        int tg = (r >> 1) & 3;
        int col = (r >> 3) & 127;
        int ks = r >> 10;
        int k0 = c * 32 + ks * 16 + h * 8 + tg * 2;
        float v0 = (k0 < 128) ? W_hh[(gate * 128 + col) * 128 + k0]
                              : W_ih[(gate * 128 + col) * 128 + (k0 - 128)];
        int k1 = k0 + 1;
        float v1 = (k1 < 128) ? W_hh[(gate * 128 + col) * 128 + k1]
                              : W_ih[(gate * 128 + col) * 128 + (k1 - 128)];
        g_WcombP[i2] = pack2(v0, v1);
        return;
    }
    long long i3 = i2 - 3LL * 8 * 2048;
    if (i3 < 3LL * NN) { g_cnt[i3] = 0; return; }
    long long i4 = i3 - 3LL * NN;
    if (i4 < NN) { g_deg[i4] = 0; g_cursor[i4] = 0; return; }
    long long i5 = i4 - NN;
    if (i5 < NG) { g_gcount[i5] = 0; return; }
    if (i5 == NG) g_scan_ctr = 0;
}

__global__ void counts_kernel(const int* __restrict__ ei, const int* __restrict__ batch) {
    int e = blockIdx.x * blockDim.x + threadIdx.x;
    if (e < NE) atomicAdd(&g_deg[ei[NE + e]], 1);
    if (e < NN) atomicAdd(&g_gcount[batch[e]], 1);
}

__global__ void scan_fused() {
    __shared__ int sh[1024];
    __shared__ int amLast;
    int tid = threadIdx.x;
    int i = blockIdx.x * 1024 + tid;
    int v = (i < NN) ? g_deg[i] : 0;
    sh[tid] = v;
    __syncthreads();
    for (int off = 1; off < 1024; off <<= 1) {
        int t = (tid >= off) ? sh[tid - off] : 0;
        __syncthreads();
        sh[tid] += t;
        __syncthreads();
    }
    if (i < NN) g_rowoff[i + 1] = sh[tid];
    if (tid == 1023) g_bsums[blockIdx.x] = sh[1023];
    __threadfence();
    if (tid == 0) {
        int t = atomicAdd(&g_scan_ctr, 1);
        amLast = (t == (int)gridDim.x - 1);
    }
    __syncthreads();
    if (amLast) {
        if (tid == 0) {
            int acc = 0;
            for (int b = 0; b < (int)gridDim.x; b++) {
                int t = g_bsums[b];
                g_bsums[b] = acc;
                acc += t;
            }
        }
        __syncthreads();
        for (int j = tid; j < NN; j += 1024)
            g_rowoff[j + 1] += g_bsums[j >> 10];
        if (tid == 0) g_rowoff[0] = 0;
    }
}

__global__ void scatter_kernel(const int* __restrict__ ei, const int* __restrict__ et) {
    if (blockIdx.x == 0 && threadIdx.x == 0) {
        int a = 0;
        g_gstart[0] = 0;
        for (int g = 0; g < NG; g++) { a += g_gcount[g]; g_gstart[g + 1] = a; }
    }
    int e = blockIdx.x * blockDim.x + threadIdx.x;
    if (e >= NE) return;
    int s = ei[e];
    int d = ei[NE + e];
    int t = et[e];
    int pos = g_rowoff[d] + atomicAdd(&g_cursor[d], 1);
    g_packed[pos] = s | (t << 20);
    atomicAdd(&g_cnt[d * 3 + t], 1);
}

// ---------------- aggregation (fp16 gather, fp32 accumulate, half2 S) ----------------
__device__ __forceinline__ void h2acc(float4& a, uint2 v) {
    float2 f0 = __half22float2(*(__half2*)&v.x);
    float2 f1 = __half22float2(*(__half2*)&v.y);
    a.x += f0.x; a.y += f0.y; a.z += f1.x; a.w += f1.y;
}

__global__ void aggregate_kernel() {
    int node = (blockIdx.x * blockDim.x + threadIdx.x) >> 5;
    int lane = threadIdx.x & 31;
    if (node >= NN) return;
    int beg = g_rowoff[node];
    int end = g_rowoff[node + 1];
    float4 a0 = make_float4(0.f, 0.f, 0.f, 0.f), a1 = a0, a2 = a0;
    const uint2* xh = (const uint2*)g_xh;
    int k = beg;
    for (; k + 4 <= end; k += 4) {
        int p0 = __ldg(&g_packed[k]);
        int p1 = __ldg(&g_packed[k + 1]);
        int p2 = __ldg(&g_packed[k + 2]);
        int p3 = __ldg(&g_packed[k + 3]);
        uint2 v0 = xh[(size_t)(p0 & 0xFFFFF) * 32 + lane];
        uint2 v1 = xh[(size_t)(p1 & 0xFFFFF) * 32 + lane];
        uint2 v2 = xh[(size_t)(p2 & 0xFFFFF) * 32 + lane];
        uint2 v3 = xh[(size_t)(p3 & 0xFFFFF) * 32 + lane];
        int t0 = p0 >> 20, t1 = p1 >> 20, t2 = p2 >> 20, t3 = p3 >> 20;
        if (t0 == 0) h2acc(a0, v0); else if (t0 == 1) h2acc(a1, v0); else h2acc(a2, v0);
        if (t1 == 0) h2acc(a0, v1); else if (t1 == 1) h2acc(a1, v1); else h2acc(a2, v1);
        if (t2 == 0) h2acc(a0, v2); else if (t2 == 1) h2acc(a1, v2); else h2acc(a2, v2);
        if (t3 == 0) h2acc(a0, v3); else if (t3 == 1) h2acc(a1, v3); else h2acc(a2, v3);
    }
    for (; k < end; k++) {
        int p = __ldg(&g_packed[k]);
        uint2 v = xh[(size_t)(p & 0xFFFFF) * 32 + lane];
        int t = p >> 20;
        if (t == 0) h2acc(a0, v); else if (t == 1) h2acc(a1, v); else h2acc(a2, v);
    }
    unsigned* Sp = g_S + (size_t)node * 192;
    *(uint2*)(Sp + lane * 2)       = make_uint2(pack2(a0.x, a0.y), pack2(a0.z, a0.w));
    *(uint2*)(Sp + 64 + lane * 2)  = make_uint2(pack2(a1.x, a1.y), pack2(a1.z, a1.w));
    *(uint2*)(Sp + 128 + lane * 2) = make_uint2(pack2(a2.x, a2.y), pack2(a2.z, a2.w));
}

// ---------------- fp16 mma ----------------
__device__ __forceinline__ void mma_f16(float c[4], unsigned a0, unsigned a1,
                                        unsigned a2, unsigned a3,
                                        unsigned b0, unsigned b1) {
    asm volatile(
        "mma.sync.aligned.m16n8k16.row.col.f32.f16.f16.f32 "
        "{%0,%1,%2,%3}, {%4,%5,%6,%7}, {%8,%9}, {%0,%1,%2,%3};\n"
        : "+f"(c[0]), "+f"(c[1]), "+f"(c[2]), "+f"(c[3])
        : "r"(a0), "r"(a1), "r"(a2), "r"(a3), "r"(b0), "r"(b1));
}

// ---------------- smem geometry (word units) ----------------
// big chunks: 32 kpairs (K=64). Triple-buffered cp.async pipeline.
#define AST2 132
#define SST3 36           // S big-chunk row stride (32 kpairs + pad)
#define BCH3 4096         // packed B big-chunk words (2 small chunks concatenated)
#define FSMEM ((128 * AST2 + 3 * 128 * SST3 + 3 * BCH3) * 4)

// streamed pre-packed-B phase; cp.async triple-buffered, one barrier per big chunk
__device__ __forceinline__ void gemm_phase(
    const unsigned* __restrict__ As, const unsigned* __restrict__ Bsh, unsigned bs_addr,
    const unsigned* __restrict__ BsrcP, int kpair0, int nch,
    int warp_m, int warp_n, int gidx, int tig, int tid,
    float acc[2][4][4], bool zero)
{
    if (zero) {
#pragma unroll
        for (int i = 0; i < 2; i++)
#pragma unroll
            for (int j = 0; j < 4; j++)
#pragma unroll
                for (int c = 0; c < 4; c++) acc[i][j][c] = 0.f;
    }

    __syncthreads();   // prior phase's readers done before overwriting buffers
    cp16(bs_addr + (0 * BCH3 + tid * 8) * 4, BsrcP + tid * 8, 16);
    cp16(bs_addr + (0 * BCH3 + tid * 8 + 4) * 4, BsrcP + tid * 8 + 4, 16);
    CP_COMMIT();
    if (nch > 1) {
        cp16(bs_addr + (1 * BCH3 + tid * 8) * 4, BsrcP + BCH3 + tid * 8, 16);
        cp16(bs_addr + (1 * BCH3 + tid * 8 + 4) * 4, BsrcP + BCH3 + tid * 8 + 4, 16);
        CP_COMMIT();
    }

    for (int c = 0; c < nch; c++) {
        if (c + 1 < nch) CP_WAIT1(); else CP_WAIT0();
        __syncthreads();
        const unsigned* bp = Bsh + (c % 3) * BCH3;
        const int kb = kpair0 + c * 32;
#pragma unroll
        for (int ks = 0; ks < 4; ks++) {
            unsigned af[2][4];
            unsigned long long bv[4];
#pragma unroll
            for (int mf = 0; mf < 2; mf++) {
                const unsigned* p = As + (warp_m + mf * 16 + gidx) * AST2 + kb + ks * 8 + tig;
                af[mf][0] = p[0];
                af[mf][1] = p[8 * AST2];
                af[mf][2] = p[4];
                af[mf][3] = p[8 * AST2 + 4];
            }
#pragma unroll
            for (int nf = 0; nf < 4; nf++)
                bv[nf] = *(const unsigned long long*)(bp + (ks >> 1) * 2048 +
                    ((((ks & 1) * 128) + warp_n + nf * 8 + gidx) * 4 + tig) * 2);
#pragma unroll
            for (int mf = 0; mf < 2; mf++)
#pragma unroll
                for (int nf = 0; nf < 4; nf++)
                    mma_f16(acc[mf][nf], af[mf][0], af[mf][1], af[mf][2], af[mf][3],
                            (unsigned)bv[nf], (unsigned)(bv[nf] >> 32));
        }
        if (c + 2 < nch) {
            int nb = (c + 2) % 3;
            cp16(bs_addr + (nb * BCH3 + tid * 8) * 4,
                 BsrcP + (c + 2) * BCH3 + tid * 8, 16);
            cp16(bs_addr + (nb * BCH3 + tid * 8 + 4) * 4,
                 BsrcP + (c + 2) * BCH3 + tid * 8 + 4, 16);
            CP_COMMIT();
        }
    }
}

__device__ __forceinline__ float sigm(float v) { return 1.f / (1.f + expf(-v)); }

// ---------------- fused round kernel ----------------
__global__ __launch_bounds__(512, 1)
void fused_round_k(const float* __restrict__ msgb,
                   const float* __restrict__ b_ih, const float* __restrict__ b_hh) {
    extern __shared__ unsigned sh_u32[];
    unsigned* Atile = sh_u32;                             // [128][AST2]
    unsigned* Ssh = sh_u32 + 128 * AST2;                  // [3][128][SST3]
    unsigned* Bsh = sh_u32 + 128 * AST2 + 3 * 128 * SST3; // [3][BCH3]
    const unsigned sbase = (unsigned)__cvta_generic_to_shared(sh_u32);
    const unsigned ss_addr = sbase + 128 * AST2 * 4;
    const unsigned bs_addr = ss_addr + 3 * 128 * SST3 * 4;

    const int tid = threadIdx.x;
    const int lane = tid & 31;
    const int wid = tid >> 5;
    const int warp_m = (wid & 3) * 32;
    const int warp_n = (wid >> 2) * 32;
    const int rowBase = blockIdx.x * 128;
    const int gidx = lane >> 2;
    const int tig = lane & 3;
    const uint4 zu4 = make_uint4(0u, 0u, 0u, 0u);

    // ---- load x tile (fp16 shadow) into Atile kpairs 0..63 : raw copy ----
    {
        int row = tid >> 2;
        int seg = tid & 3;
        int gr = rowBase + row;
        const uint4* xr = (const uint4*)(g_xh + (size_t)gr * 64);
#pragma unroll
        for (int j = 0; j < 4; j++) {
            uint4 v = (gr < NN) ? xr[seg * 4 + j] : zu4;
            *(uint4*)(Atile + row * AST2 + seg * 16 + j * 4) = v;
        }
    }

    // ---- P0: agg GEMM, A = S streamed (6 big chunks; cp.async triple-buffered) ----
    float acc2[2][4][4];
#pragma unroll
    for (int i = 0; i < 2; i++)
#pragma unroll
        for (int j = 0; j < 4; j++)
#pragma unroll
            for (int c = 0; c < 4; c++) acc2[i][j][c] = 0.f;

    {
        const int sr = tid >> 2;           // row 0..127
        const int sq = (tid & 3) * 8;      // kpair offset 0,8,16,24
        const int srow = rowBase + sr;
        const int sbytes = (srow < NN) ? 16 : 0;
        const unsigned* Srow = g_S + (size_t)srow * 192;

        // prologue: stage big chunks 0,1 (S + B together per group)
        cp16(ss_addr + (0 * 128 * SST3 + sr * SST3 + sq) * 4, Srow + sq, sbytes);
        cp16(ss_addr + (0 * 128 * SST3 + sr * SST3 + sq + 4) * 4, Srow + sq + 4, sbytes);
        cp16(bs_addr + (0 * BCH3 + tid * 8) * 4, g_WcatP + tid * 8, 16);
        cp16(bs_addr + (0 * BCH3 + tid * 8 + 4) * 4, g_WcatP + tid * 8 + 4, 16);
        CP_COMMIT();
        cp16(ss_addr + (1 * 128 * SST3 + sr * SST3 + sq) * 4, Srow + 32 + sq, sbytes);
        cp16(ss_addr + (1 * 128 * SST3 + sr * SST3 + sq + 4) * 4, Srow + 32 + sq + 4, sbytes);
        cp16(bs_addr + (1 * BCH3 + tid * 8) * 4, g_WcatP + BCH3 + tid * 8, 16);
        cp16(bs_addr + (1 * BCH3 + tid * 8 + 4) * 4, g_WcatP + BCH3 + tid * 8 + 4, 16);
        CP_COMMIT();

        for (int c = 0; c < 6; c++) {
            if (c + 1 < 6) CP_WAIT1(); else CP_WAIT0();
            __syncthreads();
            const unsigned* ap = Ssh + (c % 3) * 128 * SST3;
            const unsigned* bp = Bsh + (c % 3) * BCH3;
#pragma unroll
            for (int ks = 0; ks < 4; ks++) {
                unsigned af[2][4];
                unsigned long long bv[4];
#pragma unroll
                for (int mf = 0; mf < 2; mf++) {
                    const unsigned* p = ap + (warp_m + mf * 16 + gidx) * SST3 + ks * 8 + tig;
                    af[mf][0] = p[0];
                    af[mf][1] = p[8 * SST3];
                    af[mf][2] = p[4];
                    af[mf][3] = p[8 * SST3 + 4];
                }
#pragma unroll
                for (int nf = 0; nf < 4; nf++)
                    bv[nf] = *(const unsigned long long*)(bp + (ks >> 1) * 2048 +
                        ((((ks & 1) * 128) + warp_n + nf * 8 + gidx) * 4 + tig) * 2);
#pragma unroll
                for (int mf = 0; mf < 2; mf++)
#pragma unroll
                    for (int nf = 0; nf < 4; nf++)
                        mma_f16(acc2[mf][nf], af[mf][0], af[mf][1], af[mf][2], af[mf][3],
                                (unsigned)bv[nf], (unsigned)(bv[nf] >> 32));
            }
            if (c + 2 < 6) {
                int nb = (c + 2) % 3;
                cp16(ss_addr + (nb * 128 * SST3 + sr * SST3 + sq) * 4,
                     Srow + (c + 2) * 32 + sq, sbytes);
                cp16(ss_addr + (nb * 128 * SST3 + sr * SST3 + sq + 4) * 4,
                     Srow + (c + 2) * 32 + sq + 4, sbytes);
                cp16(bs_addr + (nb * BCH3 + tid * 8) * 4,
                     g_WcatP + (c + 2) * BCH3 + tid * 8, 16);
                cp16(bs_addr + (nb * BCH3 + tid * 8 + 4) * 4,
                     g_WcatP + (c + 2) * BCH3 + tid * 8 + 4, 16);
                CP_COMMIT();
            }
        }
    }

    // ---- P0 epilogue: agg + cnt*msgb -> Atile kpairs 64..127 ----
#pragma unroll
    for (int mf = 0; mf < 2; mf++) {
        int r0l = warp_m + mf * 16 + gidx;
        int r1l = r0l + 8;
        int r0 = rowBase + r0l, r1 = rowBase + r1l;
        float c00 = 0.f, c01 = 0.f, c02 = 0.f, c10 = 0.f, c11 = 0.f, c12 = 0.f;
        if (r0 < NN) { c00 = (float)g_cnt[r0 * 3]; c01 = (float)g_cnt[r0 * 3 + 1]; c02 = (float)g_cnt[r0 * 3 + 2]; }
        if (r1 < NN) { c10 = (float)g_cnt[r1 * 3]; c11 = (float)g_cnt[r1 * 3 + 1]; c12 = (float)g_cnt[r1 * 3 + 2]; }
#pragma unroll
        for (int nf = 0; nf < 4; nf++) {
            int col = warp_n + nf * 8 + tig * 2;
            float m00 = msgb[col], m10 = msgb[128 + col], m20 = msgb[256 + col];
            float m01 = msgb[col + 1], m11 = msgb[128 + col + 1], m21 = msgb[256 + col + 1];
            float v0 = acc2[mf][nf][0] + c00 * m00 + c01 * m10 + c02 * m20;
            float v1 = acc2[mf][nf][1] + c00 * m01 + c01 * m11 + c02 * m21;
            float w0 = acc2[mf][nf][2] + c10 * m00 + c11 * m10 + c12 * m20;
            float w1 = acc2[mf][nf][3] + c10 * m01 + c11 * m11 + c12 * m21;
            int kp = 64 + ((warp_n + nf * 8) >> 1) + tig;
            Atile[r0l * AST2 + kp] = pack2(v0, v1);
            Atile[r1l * AST2 + kp] = pack2(w0, w1);
        }
    }

    // ---- GRU phases ----
    float acc[2][4][4];
    float keep[2][4][4];

    // P1: r gate (gate 0, K=256 -> 4 big chunks)
    gemm_phase(Atile, Bsh, bs_addr, g_WcombP + 0 * 16384, 0, 4,
               warp_m, warp_n, gidx, tig, tid, acc, true);
#pragma unroll
    for (int mf = 0; mf < 2; mf++)
#pragma unroll
        for (int nf = 0; nf < 4; nf++) {
            int col = warp_n + nf * 8 + tig * 2;
            float cb0 = b_ih[col] + b_hh[col];
            float cb1 = b_ih[col + 1] + b_hh[col + 1];
            keep[mf][nf][0] = sigm(acc[mf][nf][0] + cb0);
            keep[mf][nf][1] = sigm(acc[mf][nf][1] + cb1);
            keep[mf][nf][2] = sigm(acc[mf][nf][2] + cb0);
            keep[mf][nf][3] = sigm(acc[mf][nf][3] + cb1);
        }

    // P2: t = r * (x@Whh_n + b_hh_n)  (gate 2, big chunks 0..1)
    gemm_phase(Atile, Bsh, bs_addr, g_WcombP + 2 * 16384, 0, 2,
               warp_m, warp_n, gidx, tig, tid, acc, true);
#pragma unroll
    for (int mf = 0; mf < 2; mf++)
#pragma unroll
        for (int nf = 0; nf < 4; nf++) {
            int col = warp_n + nf * 8 + tig * 2;
            float bb0 = b_hh[256 + col], bb1 = b_hh[256 + col + 1];
            keep[mf][nf][0] = keep[mf][nf][0] * (acc[mf][nf][0] + bb0);
            keep[mf][nf][1] = keep[mf][nf][1] * (acc[mf][nf][1] + bb1);
            keep[mf][nf][2] = keep[mf][nf][2] * (acc[mf][nf][2] + bb0);
            keep[mf][nf][3] = keep[mf][nf][3] * (acc[mf][nf][3] + bb1);
        }

    // P3: nv = tanh(agg@Wih_n + b_ih_n + t)  (gate 2, big chunks 2..3; A kpairs 64+)
    gemm_phase(Atile, Bsh, bs_addr, g_WcombP + 2 * 16384 + 2 * BCH3, 64, 2,
               warp_m, warp_n, gidx, tig, tid, acc, true);
#pragma unroll
    for (int mf = 0; mf < 2; mf++)
#pragma unroll
        for (int nf = 0; nf < 4; nf++) {
            int col = warp_n + nf * 8 + tig * 2;
            float bb0 = b_ih[256 + col], bb1 = b_ih[256 + col + 1];
            keep[mf][nf][0] = tanhf(acc[mf][nf][0] + bb0 + keep[mf][nf][0]);
            keep[mf][nf][1] = tanhf(acc[mf][nf][1] + bb1 + keep[mf][nf][1]);
            keep[mf][nf][2] = tanhf(acc[mf][nf][2] + bb0 + keep[mf][nf][2]);
            keep[mf][nf][3] = tanhf(acc[mf][nf][3] + bb1 + keep[mf][nf][3]);
        }

    // P4: z gate (gate 1); combine; write x (fp32) + xh (fp16 shadow)
    gemm_phase(Atile, Bsh, bs_addr, g_WcombP + 1 * 16384, 0, 4,
               warp_m, warp_n, gidx, tig, tid, acc, true);
#pragma unroll
    for (int mf = 0; mf < 2; mf++) {
        int r0 = rowBase + warp_m + mf * 16 + gidx;
        int r1 = r0 + 8;
#pragma unroll
        for (int nf = 0; nf < 4; nf++) {
            int col = warp_n + nf * 8 + tig * 2;
            float cb0 = b_ih[128 + col] + b_hh[128 + col];
            float cb1 = b_ih[128 + col + 1] + b_hh[128 + col + 1];
            float z0 = sigm(acc[mf][nf][0] + cb0);
            float z1 = sigm(acc[mf][nf][1] + cb1);
            float z2 = sigm(acc[mf][nf][2] + cb0);
            float z3 = sigm(acc[mf][nf][3] + cb1);
            if (r0 < NN) {
                float2 h = *(const float2*)(g_x + (size_t)r0 * 128 + col);
                float o0 = (1.f - z0) * keep[mf][nf][0] + z0 * h.x;
                float o1 = (1.f - z1) * keep[mf][nf][1] + z1 * h.y;
                *(float2*)(g_x + (size_t)r0 * 128 + col) = make_float2(o0, o1);
                g_xh[(size_t)r0 * 64 + (col >> 1)] = pack2(o0, o1);
            }
            if (r1 < NN) {
                float2 h = *(const float2*)(g_x + (size_t)r1 * 128 + col);
                float o2 = (1.f - z2) * keep[mf][nf][2] + z2 * h.x;
                float o3 = (1.f - z3) * keep[mf][nf][3] + z3 * h.y;
                *(float2*)(g_x + (size_t)r1 * 128 + col) = make_float2(o2, o3);
                g_xh[(size_t)r1 * 64 + (col >> 1)] = pack2(o2, o3);
            }
        }
    }
}

// ---------------- readout ----------------
__global__ void pool_kernel() {
    int g = blockIdx.x;
    int j = threadIdx.x;
    int beg = g_gstart[g], end = g_gstart[g + 1];
    float s = 0.f;
    for (int nd = beg; nd < end; nd++) s += g_x[(size_t)nd * DD + j];
    int c = end - beg;
    float cf = (c > 0) ? (float)c : 1.f;
    g_pooled[g * DD + j] = s / cf;
}

__global__ void mlp_kernel(const float* __restrict__ pW1, const float* __restrict__ pb1,
                           const float* __restrict__ pW2, const float* __restrict__ pb2,
                           float* __restrict__ out) {
    int g = blockIdx.x;
    int j = threadIdx.x;
    __shared__ float sh[128];
    float acc = pb1[j];
    const float* pr = g_pooled + g * DD;
#pragma unroll 8
    for (int i = 0; i < DD; i++) acc = fmaf(pr[i], pW1[j * DD + i], acc);
    float h = acc > 0.f ? acc : 0.f;
    sh[j] = h * pW2[j];
    __syncthreads();
    for (int s = 64; s > 0; s >>= 1) {
        if (j < s) sh[j] += sh[j + s];
        __syncthreads();
    }
    if (j == 0) out[g] = sh[0] + pb2[0];
}

// ---------------- launch ----------------
extern "C" void kernel_launch(void* const* d_in, const int* in_sizes, int n_in,
                              void* d_out, int out_size) {
    const int*   x_type   = (const int*)d_in[0];
    const int*   x_tok    = (const int*)d_in[1];
    const float* x_small  = (const float*)d_in[2];
    const int*   edge_idx = (const int*)d_in[3];
    const int*   edge_typ = (const int*)d_in[4];
    const int*   batch    = (const int*)d_in[5];
    const float* type_emb = (const float*)d_in[6];
    const float* tok_emb  = (const float*)d_in[7];
    const float* msg_W    = (const float*)d_in[8];
    const float* msg_b    = (const float*)d_in[9];
    const float* W_ih     = (const float*)d_in[10];
    const float* W_hh     = (const float*)d_in[11];
    const float* b_ih     = (const float*)d_in[12];
    const float* b_hh     = (const float*)d_in[13];
    const float* pW1      = (const float*)d_in[14];
    const float* pb1      = (const float*)d_in[15];
    const float* pW2      = (const float*)d_in[16];
    const float* pb2      = (const float*)d_in[17];
    float* out = (float*)d_out;

    cudaFuncSetAttribute(fused_round_k, cudaFuncAttributeMaxDynamicSharedMemorySize, FSMEM);

    long long mega_total = (long long)NN * 128 + 12 * 2048 + 3LL * 8 * 2048 +
                           3LL * NN + NN + NG + 1;
    int mega_blocks = (int)((mega_total + 255) / 256);

    mega_setup<<<mega_blocks, 256>>>(x_type, x_tok, x_small, type_emb, tok_emb,
                                     msg_W, W_ih, W_hh);
    counts_kernel<<<(NE + 255) / 256, 256>>>(edge_idx, batch);
    scan_fused<<<(NN + 1023) / 1024, 1024>>>();
    scatter_kernel<<<(NE + 255) / 256, 256>>>(edge_idx, edge_typ);

    const int mblk = (NN + 127) / 128;
    for (int r = 0; r < ROUNDS; r++) {
        aggregate_kernel<<<(NN * 32 + 255) / 256, 256>>>();
        fused_round_k<<<mblk, 512, FSMEM>>>(msg_b, b_ih, b_hh);
    }

    pool_kernel<<<NG, 128>>>();
    mlp_kernel<<<NG, 128>>>(pW1, pb1, pW2, pb2, out);
}

// round 13
// speedup vs baseline: 1.0695x; 1.0695x over previous
#include <cuda_runtime.h>
#include <cuda_bf16.h>
#include <cuda_fp16.h>
#include <math.h>

#define NN 100000
#define NE 600000
#define DD 128
#define TD 384
#define NG 64
#define ROUNDS 8

// ---------------- scratch ----------------
__device__ float    g_x[NN * DD];            // fp32 node state (GRU h path, pooling)
__device__ unsigned g_xh[NN * 64];           // half2-packed shadow of x (message path)
__device__ unsigned g_S[NN * 192];           // aggregated sums, packed half2
__device__ unsigned g_WcatP[12 * 2048];      // fp16 pair-packed agg weights
__device__ unsigned g_WcombP[3 * 8 * 2048];  // fp16 pair-packed gate weights
__device__ int   g_deg[NN];
__device__ int   g_rowoff[NN + 1];
__device__ int   g_cursor[NN];
__device__ int   g_packed[NE];
__device__ int   g_cnt[NN * 3];
__device__ int   g_bsums[128];
__device__ int   g_scan_ctr;
__device__ float g_pooled[NG * DD];
__device__ int   g_gcount[NG];
__device__ int   g_gstart[NG + 1];

__device__ __forceinline__ unsigned pack2(float a, float b) {
    __half2 h = __floats2half2_rn(a, b);
    return *(unsigned*)&h;
}

// ---------------- cp.async helpers ----------------
__device__ __forceinline__ void cp16(unsigned dst, const void* src, int bytes) {
    asm volatile("cp.async.ca.shared.global [%0], [%1], 16, %2;"
                 :: "r"(dst), "l"(src), "r"(bytes) : "memory");
}
#define CP_COMMIT() asm volatile("cp.async.commit_group;" ::: "memory")
#define CP_WAIT1() asm volatile("cp.async.wait_group 1;" ::: "memory")
#define CP_WAIT0() asm volatile("cp.async.wait_group 0;" ::: "memory")

// ---------------- setup ----------------
__global__ void mega_setup(const int* __restrict__ x_type, const int* __restrict__ x_tok,
                           const float* __restrict__ x_small,
                           const float* __restrict__ type_emb, const float* __restrict__ tok_emb,
                           const float* __restrict__ msg_W,
                           const float* __restrict__ W_ih, const float* __restrict__ W_hh) {
    long long idx = (long long)blockIdx.x * blockDim.x + threadIdx.x;
    const long long R0 = (long long)NN * 128;
    if (idx < R0) {
        int n = (int)(idx >> 7);
        int j = (int)(idx & 127);
        float v;
        if (j < 32)       v = type_emb[x_type[n] * 32 + j];
        else if (j < 64)  v = tok_emb[x_tok[n] * 32 + (j - 32)];
        else              v = x_small[n * 64 + (j - 64)];
        g_x[idx] = v;
        ((__half*)g_xh)[idx] = __float2half(v);
        return;
    }
    long long i1 = idx - R0;
    if (i1 < 12 * 2048) {
        int c = (int)(i1 >> 11);
        int r = (int)(i1 & 2047);
        int h = r & 1;
        int tg = (r >> 1) & 3;
        int col = (r >> 3) & 127;
        int ks = r >> 10;
        int k0 = c * 32 + ks * 16 + h * 8 + tg * 2;
        int t0 = k0 >> 7, i0 = k0 & 127;
        int k1 = k0 + 1;
        int t1 = k1 >> 7, i1b = k1 & 127;
        g_WcatP[i1] = pack2(msg_W[t0 * 16384 + col * 128 + i0],
                            msg_W[t1 * 16384 + col * 128 + i1b]);
        return;
    }
    long long i2 = i1 - 12 * 2048;
    if (i2 < 3LL * 8 * 2048) {
        int gate = (int)(i2 >> 14);
        int r2 = (int)(i2 & 16383);
        int c = r2 >> 11;
        int r = r2 & 2047;
        int h = r & 1;
        int tg = (r >> 1) & 3;
        int col = (r >> 3) & 127;
        int ks = r >> 10;
        int k0 = c * 32 + ks * 16 + h * 8 + tg * 2;
        float v0 = (k0 < 128) ? W_hh[(gate * 128 + col) * 128 + k0]
                              : W_ih[(gate * 128 + col) * 128 + (k0 - 128)];
        int k1 = k0 + 1;
        float v1 = (k1 < 128) ? W_hh[(gate * 128 + col) * 128 + k1]
                              : W_ih[(gate * 128 + col) * 128 + (k1 - 128)];
        g_WcombP[i2] = pack2(v0, v1);
        return;
    }
    long long i3 = i2 - 3LL * 8 * 2048;
    if (i3 < 3LL * NN) { g_cnt[i3] = 0; return; }
    long long i4 = i3 - 3LL * NN;
    if (i4 < NN) { g_deg[i4] = 0; g_cursor[i4] = 0; return; }
    long long i5 = i4 - NN;
    if (i5 < NG) { g_gcount[i5] = 0; return; }
    if (i5 == NG) g_scan_ctr = 0;
}

__global__ void counts_kernel(const int* __restrict__ ei, const int* __restrict__ batch) {
    int e = blockIdx.x * blockDim.x + threadIdx.x;
    if (e < NE) atomicAdd(&g_deg[ei[NE + e]], 1);
    if (e < NN) atomicAdd(&g_gcount[batch[e]], 1);
}

__global__ void scan_fused() {
    __shared__ int sh[1024];
    __shared__ int amLast;
    int tid = threadIdx.x;
    int i = blockIdx.x * 1024 + tid;
    int v = (i < NN) ? g_deg[i] : 0;
    sh[tid] = v;
    __syncthreads();
    for (int off = 1; off < 1024; off <<= 1) {
        int t = (tid >= off) ? sh[tid - off] : 0;
        __syncthreads();
        sh[tid] += t;
        __syncthreads();
    }
    if (i < NN) g_rowoff[i + 1] = sh[tid];
    if (tid == 1023) g_bsums[blockIdx.x] = sh[1023];
    __threadfence();
    if (tid == 0) {
        int t = atomicAdd(&g_scan_ctr, 1);
        amLast = (t == (int)gridDim.x - 1);
    }
    __syncthreads();
    if (amLast) {
        if (tid == 0) {
            int acc = 0;
            for (int b = 0; b < (int)gridDim.x; b++) {
                int t = g_bsums[b];
                g_bsums[b] = acc;
                acc += t;
            }
        }
        __syncthreads();
        for (int j = tid; j < NN; j += 1024)
            g_rowoff[j + 1] += g_bsums[j >> 10];
        if (tid == 0) g_rowoff[0] = 0;
    }
}

__global__ void scatter_kernel(const int* __restrict__ ei, const int* __restrict__ et) {
    if (blockIdx.x == 0 && threadIdx.x == 0) {
        int a = 0;
        g_gstart[0] = 0;
        for (int g = 0; g < NG; g++) { a += g_gcount[g]; g_gstart[g + 1] = a; }
    }
    int e = blockIdx.x * blockDim.x + threadIdx.x;
    if (e >= NE) return;
    int s = ei[e];
    int d = ei[NE + e];
    int t = et[e];
    int pos = g_rowoff[d] + atomicAdd(&g_cursor[d], 1);
    g_packed[pos] = s | (t << 20);
    atomicAdd(&g_cnt[d * 3 + t], 1);
}

// ---------------- aggregation (fp16 gather, fp32 accumulate, half2 S) ----------------
__device__ __forceinline__ void h2acc(float4& a, uint2 v) {
    float2 f0 = __half22float2(*(__half2*)&v.x);
    float2 f1 = __half22float2(*(__half2*)&v.y);
    a.x += f0.x; a.y += f0.y; a.z += f1.x; a.w += f1.y;
}

__global__ void aggregate_kernel() {
    int node = (blockIdx.x * blockDim.x + threadIdx.x) >> 5;
    int lane = threadIdx.x & 31;
    if (node >= NN) return;
    int beg = g_rowoff[node];
    int end = g_rowoff[node + 1];
    float4 a0 = make_float4(0.f, 0.f, 0.f, 0.f), a1 = a0, a2 = a0;
    const uint2* xh = (const uint2*)g_xh;
    int k = beg;
    for (; k + 4 <= end; k += 4) {
        int p0 = __ldg(&g_packed[k]);
        int p1 = __ldg(&g_packed[k + 1]);
        int p2 = __ldg(&g_packed[k + 2]);
        int p3 = __ldg(&g_packed[k + 3]);
        uint2 v0 = xh[(size_t)(p0 & 0xFFFFF) * 32 + lane];
        uint2 v1 = xh[(size_t)(p1 & 0xFFFFF) * 32 + lane];
        uint2 v2 = xh[(size_t)(p2 & 0xFFFFF) * 32 + lane];
        uint2 v3 = xh[(size_t)(p3 & 0xFFFFF) * 32 + lane];
        int t0 = p0 >> 20, t1 = p1 >> 20, t2 = p2 >> 20, t3 = p3 >> 20;
        if (t0 == 0) h2acc(a0, v0); else if (t0 == 1) h2acc(a1, v0); else h2acc(a2, v0);
        if (t1 == 0) h2acc(a0, v1); else if (t1 == 1) h2acc(a1, v1); else h2acc(a2, v1);
        if (t2 == 0) h2acc(a0, v2); else if (t2 == 1) h2acc(a1, v2); else h2acc(a2, v2);
        if (t3 == 0) h2acc(a0, v3); else if (t3 == 1) h2acc(a1, v3); else h2acc(a2, v3);
    }
    for (; k < end; k++) {
        int p = __ldg(&g_packed[k]);
        uint2 v = xh[(size_t)(p & 0xFFFFF) * 32 + lane];
        int t = p >> 20;
        if (t == 0) h2acc(a0, v); else if (t == 1) h2acc(a1, v); else h2acc(a2, v);
    }
    unsigned* Sp = g_S + (size_t)node * 192;
    *(uint2*)(Sp + lane * 2)       = make_uint2(pack2(a0.x, a0.y), pack2(a0.z, a0.w));
    *(uint2*)(Sp + 64 + lane * 2)  = make_uint2(pack2(a1.x, a1.y), pack2(a1.z, a1.w));
    *(uint2*)(Sp + 128 + lane * 2) = make_uint2(pack2(a2.x, a2.y), pack2(a2.z, a2.w));
}

// ---------------- fp16 mma ----------------
__device__ __forceinline__ void mma_f16(float c[4], unsigned a0, unsigned a1,
                                        unsigned a2, unsigned a3,
                                        unsigned b0, unsigned b1) {
    asm volatile(
        "mma.sync.aligned.m16n8k16.row.col.f32.f16.f16.f32 "
        "{%0,%1,%2,%3}, {%4,%5,%6,%7}, {%8,%9}, {%0,%1,%2,%3};\n"
        : "+f"(c[0]), "+f"(c[1]), "+f"(c[2]), "+f"(c[3])
        : "r"(a0), "r"(a1), "r"(a2), "r"(a3), "r"(b0), "r"(b1));
}

// ---------------- smem geometry (word units); 64-row tiles, 256 thr, occ 2 ----------------
#define MROWS 64
#define AST2 132
#define SST2 20
#define BCH2 2048
#define FSMEM ((MROWS * AST2 + 3 * MROWS * SST2 + 3 * BCH2) * 4)

// streamed pre-packed-B phase; cp.async triple-buffered, one barrier per chunk
__device__ __forceinline__ void gemm_phase(
    const unsigned* __restrict__ As, const unsigned* __restrict__ Bsh, unsigned bs_addr,
    const unsigned* __restrict__ BsrcP, int kpair0, int nch,
    int warp_m, int warp_n, int gidx, int tig, int tid,
    float acc[2][4][4], bool zero)
{
    if (zero) {
#pragma unroll
        for (int i = 0; i < 2; i++)
#pragma unroll
            for (int j = 0; j < 4; j++)
#pragma unroll
                for (int c = 0; c < 4; c++) acc[i][j][c] = 0.f;
    }

    __syncthreads();   // prior phase's readers done before overwriting buffers
    cp16(bs_addr + (0 * BCH2 + tid * 8) * 4, BsrcP + tid * 8, 16);
    cp16(bs_addr + (0 * BCH2 + tid * 8 + 4) * 4, BsrcP + tid * 8 + 4, 16);
    CP_COMMIT();
    if (nch > 1) {
        cp16(bs_addr + (1 * BCH2 + tid * 8) * 4, BsrcP + BCH2 + tid * 8, 16);
        cp16(bs_addr + (1 * BCH2 + tid * 8 + 4) * 4, BsrcP + BCH2 + tid * 8 + 4, 16);
        CP_COMMIT();
    }

    for (int c = 0; c < nch; c++) {
        if (c + 1 < nch) CP_WAIT1(); else CP_WAIT0();
        __syncthreads();
        const unsigned* bp = Bsh + (c % 3) * BCH2;
        const int kb = kpair0 + c * 16;
#pragma unroll
        for (int ks = 0; ks < 2; ks++) {
            unsigned af[2][4];
            unsigned long long bv[4];
#pragma unroll
            for (int mf = 0; mf < 2; mf++) {
                const unsigned* p = As + (warp_m + mf * 16 + gidx) * AST2 + kb + ks * 8 + tig;
                af[mf][0] = p[0];
                af[mf][1] = p[8 * AST2];
                af[mf][2] = p[4];
                af[mf][3] = p[8 * AST2 + 4];
            }
#pragma unroll
            for (int nf = 0; nf < 4; nf++)
                bv[nf] = *(const unsigned long long*)(bp +
                    (((ks * 128) + warp_n + nf * 8 + gidx) * 4 + tig) * 2);
#pragma unroll
            for (int mf = 0; mf < 2; mf++)
#pragma unroll
                for (int nf = 0; nf < 4; nf++)
                    mma_f16(acc[mf][nf], af[mf][0], af[mf][1], af[mf][2], af[mf][3],
                            (unsigned)bv[nf], (unsigned)(bv[nf] >> 32));
        }
        if (c + 2 < nch) {
            int nb = (c + 2) % 3;
            cp16(bs_addr + (nb * BCH2 + tid * 8) * 4,
                 BsrcP + (c + 2) * BCH2 + tid * 8, 16);
            cp16(bs_addr + (nb * BCH2 + tid * 8 + 4) * 4,
                 BsrcP + (c + 2) * BCH2 + tid * 8 + 4, 16);
            CP_COMMIT();
        }
    }
}

__device__ __forceinline__ float sigm(float v) { return 1.f / (1.f + expf(-v)); }

// ---------------- fused round kernel (64-row tiles, 256 threads, occ 2) ----------------
__global__ __launch_bounds__(256, 2)
void fused_round_k(const float* __restrict__ msgb,
                   const float* __restrict__ b_ih, const float* __restrict__ b_hh) {
    extern __shared__ unsigned sh_u32[];
    unsigned* Atile = sh_u32;                               // [64][AST2]
    unsigned* Ssh = sh_u32 + MROWS * AST2;                  // [3][64][SST2]
    unsigned* Bsh = sh_u32 + MROWS * AST2 + 3 * MROWS * SST2; // [3][BCH2]
    const unsigned sbase = (unsigned)__cvta_generic_to_shared(sh_u32);
    const unsigned ss_addr = sbase + MROWS * AST2 * 4;
    const unsigned bs_addr = ss_addr + 3 * MROWS * SST2 * 4;

    const int tid = threadIdx.x;
    const int lane = tid & 31;
    const int wid = tid >> 5;                 // 0..7
    const int warp_m = (wid & 1) * 32;        // 2 m-tiles of 32 rows
    const int warp_n = (wid >> 1) * 32;       // 4 n-tiles of 32 cols
    const int rowBase = blockIdx.x * MROWS;
    const int gidx = lane >> 2;
    const int tig = lane & 3;
    const uint4 zu4 = make_uint4(0u, 0u, 0u, 0u);

    // ---- load x tile (fp16 shadow) into Atile kpairs 0..63 : raw copy ----
    {
        int row = tid >> 2;          // 0..63
        int seg = tid & 3;
        int gr = rowBase + row;
        const uint4* xr = (const uint4*)(g_xh + (size_t)gr * 64);
#pragma unroll
        for (int j = 0; j < 4; j++) {
            uint4 v = (gr < NN) ? xr[seg * 4 + j] : zu4;
            *(uint4*)(Atile + row * AST2 + seg * 16 + j * 4) = v;
        }
    }

    // ---- P0: agg GEMM, A = S streamed (12 chunks; cp.async triple-buffered) ----
    float acc2[2][4][4];
#pragma unroll
    for (int i = 0; i < 2; i++)
#pragma unroll
        for (int j = 0; j < 4; j++)
#pragma unroll
            for (int c = 0; c < 4; c++) acc2[i][j][c] = 0.f;

    {
        const int sr = tid >> 2;           // row 0..63
        const int sq = (tid & 3) * 4;      // kpair quad 0,4,8,12
        const int srow = rowBase + sr;
        const int sbytes = (srow < NN) ? 16 : 0;
        const unsigned* Srow = g_S + (size_t)srow * 192;

        // prologue: stage chunks 0,1 (S + B together per group)
        cp16(ss_addr + (0 * MROWS * SST2 + sr * SST2 + sq) * 4, Srow + sq, sbytes);
        cp16(bs_addr + (0 * BCH2 + tid * 8) * 4, g_WcatP + tid * 8, 16);
        cp16(bs_addr + (0 * BCH2 + tid * 8 + 4) * 4, g_WcatP + tid * 8 + 4, 16);
        CP_COMMIT();
        cp16(ss_addr + (1 * MROWS * SST2 + sr * SST2 + sq) * 4, Srow + 16 + sq, sbytes);
        cp16(bs_addr + (1 * BCH2 + tid * 8) * 4, g_WcatP + BCH2 + tid * 8, 16);
        cp16(bs_addr + (1 * BCH2 + tid * 8 + 4) * 4, g_WcatP + BCH2 + tid * 8 + 4, 16);
        CP_COMMIT();

        for (int c = 0; c < 12; c++) {
            if (c + 1 < 12) CP_WAIT1(); else CP_WAIT0();
            __syncthreads();
            const unsigned* ap = Ssh + (c % 3) * MROWS * SST2;
            const unsigned* bp = Bsh + (c % 3) * BCH2;
#pragma unroll
            for (int ks = 0; ks < 2; ks++) {
                unsigned af[2][4];
                unsigned long long bv[4];
#pragma unroll
                for (int mf = 0; mf < 2; mf++) {
                    const unsigned* p = ap + (warp_m + mf * 16 + gidx) * SST2 + ks * 8 + tig;
                    af[mf][0] = p[0];
                    af[mf][1] = p[8 * SST2];
                    af[mf][2] = p[4];
                    af[mf][3] = p[8 * SST2 + 4];
                }
#pragma unroll
                for (int nf = 0; nf < 4; nf++)
                    bv[nf] = *(const unsigned long long*)(bp +
                        (((ks * 128) + warp_n + nf * 8 + gidx) * 4 + tig) * 2);
#pragma unroll
                for (int mf = 0; mf < 2; mf++)
#pragma unroll
                    for (int nf = 0; nf < 4; nf++)
                        mma_f16(acc2[mf][nf], af[mf][0], af[mf][1], af[mf][2], af[mf][3],
                                (unsigned)bv[nf], (unsigned)(bv[nf] >> 32));
            }
            if (c + 2 < 12) {
                int nb = (c + 2) % 3;
                cp16(ss_addr + (nb * MROWS * SST2 + sr * SST2 + sq) * 4,
                     Srow + (c + 2) * 16 + sq, sbytes);
                cp16(bs_addr + (nb * BCH2 + tid * 8) * 4,
                     g_WcatP + (c + 2) * BCH2 + tid * 8, 16);
                cp16(bs_addr + (nb * BCH2 + tid * 8 + 4) * 4,
                     g_WcatP + (c + 2) * BCH2 + tid * 8 + 4, 16);
                CP_COMMIT();
            }
        }
    }

    // ---- P0 epilogue: agg + cnt*msgb -> Atile kpairs 64..127 ----
#pragma unroll
    for (int mf = 0; mf < 2; mf++) {
        int r0l = warp_m + mf * 16 + gidx;
        int r1l = r0l + 8;
        int r0 = rowBase + r0l, r1 = rowBase + r1l;
        float c00 = 0.f, c01 = 0.f, c02 = 0.f, c10 = 0.f, c11 = 0.f, c12 = 0.f;
        if (r0 < NN) { c00 = (float)g_cnt[r0 * 3]; c01 = (float)g_cnt[r0 * 3 + 1]; c02 = (float)g_cnt[r0 * 3 + 2]; }
        if (r1 < NN) { c10 = (float)g_cnt[r1 * 3]; c11 = (float)g_cnt[r1 * 3 + 1]; c12 = (float)g_cnt[r1 * 3 + 2]; }
#pragma unroll
        for (int nf = 0; nf < 4; nf++) {
            int col = warp_n + nf * 8 + tig * 2;
            float m00 = msgb[col], m10 = msgb[128 + col], m20 = msgb[256 + col];
            float m01 = msgb[col + 1], m11 = msgb[128 + col + 1], m21 = msgb[256 + col + 1];
            float v0 = acc2[mf][nf][0] + c00 * m00 + c01 * m10 + c02 * m20;
            float v1 = acc2[mf][nf][1] + c00 * m01 + c01 * m11 + c02 * m21;
            float w0 = acc2[mf][nf][2] + c10 * m00 + c11 * m10 + c12 * m20;
            float w1 = acc2[mf][nf][3] + c10 * m01 + c11 * m11 + c12 * m21;
            int kp = 64 + ((warp_n + nf * 8) >> 1) + tig;
            Atile[r0l * AST2 + kp] = pack2(v0, v1);
            Atile[r1l * AST2 + kp] = pack2(w0, w1);
        }
    }

    // ---- GRU phases ----
    float acc[2][4][4];
    float keep[2][4][4];

    // P1: r gate
    gemm_phase(Atile, Bsh, bs_addr, g_WcombP + 0 * 16384, 0, 8,
               warp_m, warp_n, gidx, tig, tid, acc, true);
#pragma unroll
    for (int mf = 0; mf < 2; mf++)
#pragma unroll
        for (int nf = 0; nf < 4; nf++) {
            int col = warp_n + nf * 8 + tig * 2;
            float cb0 = b_ih[col] + b_hh[col];
            float cb1 = b_ih[col + 1] + b_hh[col + 1];
            keep[mf][nf][0] = sigm(acc[mf][nf][0] + cb0);
            keep[mf][nf][1] = sigm(acc[mf][nf][1] + cb1);
            keep[mf][nf][2] = sigm(acc[mf][nf][2] + cb0);
            keep[mf][nf][3] = sigm(acc[mf][nf][3] + cb1);
        }

    // P2: t = r * (x@Whh_n + b_hh_n)
    gemm_phase(Atile, Bsh, bs_addr, g_WcombP + 2 * 16384, 0, 4,
               warp_m, warp_n, gidx, tig, tid, acc, true);
#pragma unroll
    for (int mf = 0; mf < 2; mf++)
#pragma unroll
        for (int nf = 0; nf < 4; nf++) {
            int col = warp_n + nf * 8 + tig * 2;
            float bb0 = b_hh[256 + col], bb1 = b_hh[256 + col + 1];
            keep[mf][nf][0] = keep[mf][nf][0] * (acc[mf][nf][0] + bb0);
            keep[mf][nf][1] = keep[mf][nf][1] * (acc[mf][nf][1] + bb1);
            keep[mf][nf][2] = keep[mf][nf][2] * (acc[mf][nf][2] + bb0);
            keep[mf][nf][3] = keep[mf][nf][3] * (acc[mf][nf][3] + bb1);
        }

    // P3: nv = tanh(agg@Wih_n + b_ih_n + t)
    gemm_phase(Atile, Bsh, bs_addr, g_WcombP + 2 * 16384 + 4 * BCH2, 64, 4,
               warp_m, warp_n, gidx, tig, tid, acc, true);
#pragma unroll
    for (int mf = 0; mf < 2; mf++)
#pragma unroll
        for (int nf = 0; nf < 4; nf++) {
            int col = warp_n + nf * 8 + tig * 2;
            float bb0 = b_ih[256 + col], bb1 = b_ih[256 + col + 1];
            keep[mf][nf][0] = tanhf(acc[mf][nf][0] + bb0 + keep[mf][nf][0]);
            keep[mf][nf][1] = tanhf(acc[mf][nf][1] + bb1 + keep[mf][nf][1]);
            keep[mf][nf][2] = tanhf(acc[mf][nf][2] + bb0 + keep[mf][nf][2]);
            keep[mf][nf][3] = tanhf(acc[mf][nf][3] + bb1 + keep[mf][nf][3]);
        }

    // P4: z gate; combine; write x (fp32) + xh (fp16 shadow)
    gemm_phase(Atile, Bsh, bs_addr, g_WcombP + 1 * 16384, 0, 8,
               warp_m, warp_n, gidx, tig, tid, acc, true);
#pragma unroll
    for (int mf = 0; mf < 2; mf++) {
        int r0 = rowBase + warp_m + mf * 16 + gidx;
        int r1 = r0 + 8;
#pragma unroll
        for (int nf = 0; nf < 4; nf++) {
            int col = warp_n + nf * 8 + tig * 2;
            float cb0 = b_ih[128 + col] + b_hh[128 + col];
            float cb1 = b_ih[128 + col + 1] + b_hh[128 + col + 1];
            float z0 = sigm(acc[mf][nf][0] + cb0);
            float z1 = sigm(acc[mf][nf][1] + cb1);
            float z2 = sigm(acc[mf][nf][2] + cb0);
            float z3 = sigm(acc[mf][nf][3] + cb1);
            if (r0 < NN) {
                float2 h = *(const float2*)(g_x + (size_t)r0 * 128 + col);
                float o0 = (1.f - z0) * keep[mf][nf][0] + z0 * h.x;
                float o1 = (1.f - z1) * keep[mf][nf][1] + z1 * h.y;
                *(float2*)(g_x + (size_t)r0 * 128 + col) = make_float2(o0, o1);
                g_xh[(size_t)r0 * 64 + (col >> 1)] = pack2(o0, o1);
            }
            if (r1 < NN) {
                float2 h = *(const float2*)(g_x + (size_t)r1 * 128 + col);
                float o2 = (1.f - z2) * keep[mf][nf][2] + z2 * h.x;
                float o3 = (1.f - z3) * keep[mf][nf][3] + z3 * h.y;
                *(float2*)(g_x + (size_t)r1 * 128 + col) = make_float2(o2, o3);
                g_xh[(size_t)r1 * 64 + (col >> 1)] = pack2(o2, o3);
            }
        }
    }
}

// ---------------- readout ----------------
__global__ void pool_kernel() {
    int g = blockIdx.x;
    int j = threadIdx.x;
    int beg = g_gstart[g], end = g_gstart[g + 1];
    float s = 0.f;
    for (int nd = beg; nd < end; nd++) s += g_x[(size_t)nd * DD + j];
    int c = end - beg;
    float cf = (c > 0) ? (float)c : 1.f;
    g_pooled[g * DD + j] = s / cf;
}

__global__ void mlp_kernel(const float* __restrict__ pW1, const float* __restrict__ pb1,
                           const float* __restrict__ pW2, const float* __restrict__ pb2,
                           float* __restrict__ out) {
    int g = blockIdx.x;
    int j = threadIdx.x;
    __shared__ float sh[128];
    float acc = pb1[j];
    const float* pr = g_pooled + g * DD;
#pragma unroll 8
    for (int i = 0; i < DD; i++) acc = fmaf(pr[i], pW1[j * DD + i], acc);
    float h = acc > 0.f ? acc : 0.f;
    sh[j] = h * pW2[j];
    __syncthreads();
    for (int s = 64; s > 0; s >>= 1) {
        if (j < s) sh[j] += sh[j + s];
        __syncthreads();
    }
    if (j == 0) out[g] = sh[0] + pb2[0];
}

// ---------------- launch ----------------
extern "C" void kernel_launch(void* const* d_in, const int* in_sizes, int n_in,
                              void* d_out, int out_size) {
    const int*   x_type   = (const int*)d_in[0];
    const int*   x_tok    = (const int*)d_in[1];
    const float* x_small  = (const float*)d_in[2];
    const int*   edge_idx = (const int*)d_in[3];
    const int*   edge_typ = (const int*)d_in[4];
    const int*   batch    = (const int*)d_in[5];
    const float* type_emb = (const float*)d_in[6];
    const float* tok_emb  = (const float*)d_in[7];
    const float* msg_W    = (const float*)d_in[8];
    const float* msg_b    = (const float*)d_in[9];
    const float* W_ih     = (const float*)d_in[10];
    const float* W_hh     = (const float*)d_in[11];
    const float* b_ih     = (const float*)d_in[12];
    const float* b_hh     = (const float*)d_in[13];
    const float* pW1      = (const float*)d_in[14];
    const float* pb1      = (const float*)d_in[15];
    const float* pW2      = (const float*)d_in[16];
    const float* pb2      = (const float*)d_in[17];
    float* out = (float*)d_out;

    cudaFuncSetAttribute(fused_round_k, cudaFuncAttributeMaxDynamicSharedMemorySize, FSMEM);

    long long mega_total = (long long)NN * 128 + 12 * 2048 + 3LL * 8 * 2048 +
                           3LL * NN + NN + NG + 1;
    int mega_blocks = (int)((mega_total + 255) / 256);

    mega_setup<<<mega_blocks, 256>>>(x_type, x_tok, x_small, type_emb, tok_emb,
                                     msg_W, W_ih, W_hh);
    counts_kernel<<<(NE + 255) / 256, 256>>>(edge_idx, batch);
    scan_fused<<<(NN + 1023) / 1024, 1024>>>();
    scatter_kernel<<<(NE + 255) / 256, 256>>>(edge_idx, edge_typ);

    const int mblk = (NN + MROWS - 1) / MROWS;
    for (int r = 0; r < ROUNDS; r++) {
        aggregate_kernel<<<(NN * 32 + 255) / 256, 256>>>();
        fused_round_k<<<mblk, 256, FSMEM>>>(msg_b, b_ih, b_hh);
    }

    pool_kernel<<<NG, 128>>>();
    mlp_kernel<<<NG, 128>>>(pW1, pb1, pW2, pb2, out);
}